// round 6
// baseline (speedup 1.0000x reference)
#include <cuda_runtime.h>
#include <cstdint>

// Problem dims
#define HWX  16384      // 128*128
#define CHWX 1048576    // 64*128*128
#define TOTX 8388608    // 8*64*128*128

// ---------------- device scratch (allocation-free rule: device globals) ----
__device__ __align__(16) float g_hs [TOTX];   // south row-scan, natural [b][c][h][w]
__device__ __align__(16) float g_hn [TOTX];   // north row-scan, natural
__device__ __align__(16) float g_hsT[TOTX];   // [b][c][w][h]
__device__ __align__(16) float g_hnT[TOTX];
__device__ __align__(16) float g_yT [TOTX];   // y transposed [b][c][w][h]
__device__ __align__(16) float g_col[4][TOTX];// per-direction col-scan output, [b][c][w][h]

#define FMA4(acc, s, v) do { (acc).x += (s)*(v).x; (acc).y += (s)*(v).y; \
                             (acc).z += (s)*(v).z; (acc).w += (s)*(v).w; } while(0)

__device__ __forceinline__ float4 relu4(float4 v) {
    v.x = fmaxf(v.x, 0.f); v.y = fmaxf(v.y, 0.f);
    v.z = fmaxf(v.z, 0.f); v.w = fmaxf(v.w, 0.f);
    return v;
}

// DSMEM scalar store into peer CTA's shared memory (cluster rank `rank`)
__device__ __forceinline__ void dsmem_store(float* laddr, int rank, float v) {
    uint32_t la = (uint32_t)__cvta_generic_to_shared(laddr);
    uint32_t ra;
    asm volatile("mapa.shared::cluster.u32 %0, %1, %2;" : "=r"(ra) : "r"(la), "r"(rank));
    asm volatile("st.shared::cluster.f32 [%0], %1;" :: "r"(ra), "f"(v) : "memory");
}

// ===========================================================================
// Kernel 1: row scans (south dir=0, north dir=1).
// grid (8 w-tiles, 8 batch, 2 dirs), 256 threads.
// h_i = relu(Wa@x_i + ba + (Wb@h_prev + bb) * y_adj), state [64c x 16w] in smem.
// ===========================================================================
__global__ void __launch_bounds__(256, 1) row_scan_kernel(
    const float* __restrict__ x, const float* __restrict__ y,
    const float* __restrict__ Wc, const float* __restrict__ bc)
{
    __shared__ __align__(16) float sWaT[4096];  // [c][o]
    __shared__ __align__(16) float sWbT[4096];
    __shared__ __align__(16) float sh[1024];    // [c][16w] state
    __shared__ __align__(16) float sx[1024];
    __shared__ __align__(16) float sy[1024];
    __shared__ float sba[64], sbb[64];

    const int dir = blockIdx.z;          // 0 = south (top->bottom), 1 = north
    const int b   = blockIdx.y;
    const int w0  = blockIdx.x * 16;
    const int t   = threadIdx.x;

    const int ka = dir ? 8 : 0;          // Wc[0],Wc[1] south; Wc[8],Wc[9] north
    const float* Wa = Wc + ka * 4096;
    const float* Wb = Wc + (ka + 1) * 4096;
    for (int idx = t; idx < 4096; idx += 256) {
        int o = idx >> 6, c = idx & 63;
        sWaT[c * 64 + o] = Wa[idx];
        sWbT[c * 64 + o] = Wb[idx];
    }
    if (t < 64) { sba[t] = bc[ka * 64 + t]; sbb[t] = bc[(ka + 1) * 64 + t]; }

    const float* xb = x + b * CHWX + w0;
    const float* yb = y + b * CHWX + w0;
    float* hb = (dir ? g_hn : g_hs) + b * CHWX + w0;

    const int lc = t >> 2;               // loader: channel
    const int lw = (t & 3) * 4;          // loader: w offset (float4)

    // boundary row: south row0 = x (no relu); north row127 = relu(x)
    {
        const int r0 = dir ? 127 : 0;
        float4 v = *(const float4*)(xb + lc * HWX + r0 * 128 + lw);
        if (dir) v = relu4(v);
        *(float4*)(sh + lc * 16 + lw) = v;
        *(float4*)(hb + lc * HWX + r0 * 128 + lw) = v;
    }
    __syncthreads();

    const int o   = t >> 2;              // compute: 1 out-channel per thread
    const int wq4 = (t & 3) * 4;         // compute: 4 w per thread

    for (int i = 1; i < 128; ++i) {
        const int r  = dir ? 127 - i : i;
        const int yr = dir ? r + 1 : r - 1;
        *(float4*)(sx + lc * 16 + lw) = *(const float4*)(xb + lc * HWX + r  * 128 + lw);
        *(float4*)(sy + lc * 16 + lw) = *(const float4*)(yb + lc * HWX + yr * 128 + lw);
        __syncthreads();

        float4 aa = make_float4(0.f, 0.f, 0.f, 0.f);
        float4 ab = make_float4(0.f, 0.f, 0.f, 0.f);
        #pragma unroll 16
        for (int c = 0; c < 64; ++c) {
            float4 xv = *(const float4*)(sx + c * 16 + wq4);
            float4 hv = *(const float4*)(sh + c * 16 + wq4);
            float wa = sWaT[c * 64 + o];
            float wb = sWbT[c * 64 + o];
            FMA4(aa, wa, xv);
            FMA4(ab, wb, hv);
        }
        float4 yv = *(const float4*)(sy + o * 16 + wq4);
        const float ba_ = sba[o], bb_ = sbb[o];
        float4 hnew;
        hnew.x = fmaxf(aa.x + ba_ + (ab.x + bb_) * yv.x, 0.f);
        hnew.y = fmaxf(aa.y + ba_ + (ab.y + bb_) * yv.y, 0.f);
        hnew.z = fmaxf(aa.z + ba_ + (ab.z + bb_) * yv.z, 0.f);
        hnew.w = fmaxf(aa.w + ba_ + (ab.w + bb_) * yv.w, 0.f);
        __syncthreads();
        *(float4*)(sh + o * 16 + wq4) = hnew;
        *(float4*)(hb + o * HWX + r * 128 + wq4) = hnew;
    }
}

// ===========================================================================
// Kernel 2: batched 128x128 transpose of last two dims.
// blockIdx.z: [0,512)=y->yT, [512,1024)=hs->hsT, [1024,1536)=hn->hnT
// ===========================================================================
__global__ void __launch_bounds__(256, 1) transpose3_kernel(const float* __restrict__ ysrc)
{
    __shared__ float tile[32][33];
    const int mode = blockIdx.z >> 9;
    const int n    = blockIdx.z & 511;
    const float* src = (mode == 0 ? ysrc : (mode == 1 ? g_hs : g_hn)) + n * HWX;
    float*       dst = (mode == 0 ? g_yT : (mode == 1 ? g_hsT : g_hnT)) + n * HWX;
    const int r0 = blockIdx.y * 32, c0 = blockIdx.x * 32;
    const int tx = threadIdx.x & 31, ty = (threadIdx.x >> 5) * 4;
    #pragma unroll
    for (int k = 0; k < 4; ++k) tile[ty + k][tx] = src[(r0 + ty + k) * 128 + c0 + tx];
    __syncthreads();
    #pragma unroll
    for (int k = 0; k < 4; ++k) dst[(c0 + ty + k) * 128 + r0 + tx] = tile[tx][ty + k];
}

// ===========================================================================
// Kernel 3: column scans, all 4 directions in one launch.
// grid (4 H-chunks [cluster], 8 batch, 4 dirs), cluster (4,1,1), 256 threads.
// Each CTA owns 32 H-rows; per step exchanges one gated boundary row with
// its H-neighbor via DSMEM (parity-2 halo) + barrier.cluster.
// c_j = relu(Wa@base_j + ba + (Wb@c_prev + bb)*y_prev + gamma*shift((Wt@c_prev + bt)*y_prev))
// ===========================================================================
extern __shared__ __align__(16) float smcol[];

__global__ void __launch_bounds__(256, 1) __cluster_dims__(4, 1, 1)
col_scan_kernel(const float* __restrict__ Wc, const float* __restrict__ bc,
                const float* __restrict__ gms)
{
    float* sWtT = smcol;            // [c][o] 4096
    float* sWaT = smcol + 4096;
    float* sWbT = smcol + 8192;
    float* cp   = smcol + 12288;    // state c_prev [64c][32h]
    float* bs   = smcol + 14336;    // base column tile [64c][32h]
    float* sg   = smcol + 16384;    // gated [64o][32h]
    float* halo = smcol + 18432;    // [2 parity][64 o]
    float* sbt  = smcol + 18560;
    float* sba  = smcol + 18624;
    float* sbb  = smcol + 18688;    // total 18752 floats = 75008 B

    const int dir = blockIdx.z;     // 0 hse, 1 hsw, 2 hne, 3 hnw
    const int b   = blockIdx.y;
    const int cx  = blockIdx.x;     // cluster rank (grid.x == cluster.x == 4)
    const int r0  = cx * 32;
    const int t   = threadIdx.x;

    int kt;
    if (dir == 0) kt = 2; else if (dir == 1) kt = 5; else if (dir == 2) kt = 10; else kt = 13;
    const int  wdir  = (dir & 1) ? -1 : 1;   // east vs west scan over W
    const bool shup  = (dir >= 2);           // shift_up for hne/hnw
    const float gamma = gms[dir];

    for (int idx = t; idx < 4096; idx += 256) {
        int o = idx >> 6, c = idx & 63;
        sWtT[c * 64 + o] = Wc[kt * 4096 + idx];
        sWaT[c * 64 + o] = Wc[(kt + 1) * 4096 + idx];
        sWbT[c * 64 + o] = Wc[(kt + 2) * 4096 + idx];
    }
    if (t < 64) {
        sbt[t] = bc[kt * 64 + t];
        sba[t] = bc[(kt + 1) * 64 + t];
        sbb[t] = bc[(kt + 2) * 64 + t];
    }

    const float* baseb = ((dir < 2) ? g_hsT : g_hnT) + b * CHWX + r0;  // [c][w][h]
    const float* yTb   = g_yT + b * CHWX + r0;
    float*       outb  = g_col[dir] + b * CHWX + r0;

    const int lc = t >> 2;             // loader: channel
    const int lh = (t & 3) * 8;        // loader: 8 h per thread

    // init column
    {
        const int j0 = (wdir > 0) ? 0 : 127;
        #pragma unroll
        for (int kk = 0; kk < 2; ++kk) {
            float4 v = relu4(*(const float4*)(baseb + lc * HWX + j0 * 128 + lh + kk * 4));
            *(float4*)(cp + lc * 32 + lh + kk * 4) = v;
            *(float4*)(outb + lc * HWX + j0 * 128 + lh + kk * 4) = v;
        }
    }
    __syncthreads();

    const int hq = (t & 7) * 4;        // compute: 4 local h rows
    const int o  = (t >> 3) * 2;       // compute: 2 out-channels

    for (int jj = 1; jj < 128; ++jj) {
        const int j  = (wdir > 0) ? jj : 127 - jj;
        const int yj = j - wdir;

        // load base column j
        #pragma unroll
        for (int kk = 0; kk < 2; ++kk)
            *(float4*)(bs + lc * 32 + lh + kk * 4) =
                *(const float4*)(baseb + lc * HWX + j * 128 + lh + kk * 4);
        __syncthreads();

        float4 z = make_float4(0.f, 0.f, 0.f, 0.f);
        float4 aT0 = z, aT1 = z, aA0 = z, aA1 = z, aB0 = z, aB1 = z;
        #pragma unroll 8
        for (int c = 0; c < 64; ++c) {
            float4 bv = *(const float4*)(bs + c * 32 + hq);
            float4 pv = *(const float4*)(cp + c * 32 + hq);
            float wt0 = sWtT[c * 64 + o], wt1 = sWtT[c * 64 + o + 1];
            float wa0 = sWaT[c * 64 + o], wa1 = sWaT[c * 64 + o + 1];
            float wb0 = sWbT[c * 64 + o], wb1 = sWbT[c * 64 + o + 1];
            FMA4(aT0, wt0, pv); FMA4(aT1, wt1, pv);
            FMA4(aA0, wa0, bv); FMA4(aA1, wa1, bv);
            FMA4(aB0, wb0, pv); FMA4(aB1, wb1, pv);
        }

        // gating factor y_prev (per output channel, h-contiguous)
        float4 y0 = *(const float4*)(yTb + o * HWX + yj * 128 + hq);
        float4 y1 = *(const float4*)(yTb + (o + 1) * HWX + yj * 128 + hq);
        const float bt0 = sbt[o], bt1 = sbt[o + 1];
        float4 g0, g1;
        g0.x = (aT0.x + bt0) * y0.x; g0.y = (aT0.y + bt0) * y0.y;
        g0.z = (aT0.z + bt0) * y0.z; g0.w = (aT0.w + bt0) * y0.w;
        g1.x = (aT1.x + bt1) * y1.x; g1.y = (aT1.y + bt1) * y1.y;
        g1.z = (aT1.z + bt1) * y1.z; g1.w = (aT1.w + bt1) * y1.w;
        *(float4*)(sg + o * 32 + hq) = g0;
        *(float4*)(sg + (o + 1) * 32 + hq) = g1;

        // export boundary gated row to H-neighbor's halo (parity double-buffer)
        const int par = (jj & 1) * 64;
        if (!shup) {             // shift_down: my last row -> cx+1
            if (hq == 28 && cx < 3) {
                dsmem_store(halo + par + o,     cx + 1, g0.w);
                dsmem_store(halo + par + o + 1, cx + 1, g1.w);
            }
        } else {                 // shift_up: my first row -> cx-1
            if (hq == 0 && cx > 0) {
                dsmem_store(halo + par + o,     cx - 1, g0.x);
                dsmem_store(halo + par + o + 1, cx - 1, g1.x);
            }
        }
        asm volatile("barrier.cluster.arrive.aligned;" ::: "memory");
        asm volatile("barrier.cluster.wait.aligned;"   ::: "memory");

        // shifted gated
        float4 s0, s1;
        if (!shup) {             // shifted[h] = gated[h-1], 0 at global h=0
            float m0, m1;
            if (hq > 0)      { m0 = sg[o * 32 + hq - 1]; m1 = sg[(o + 1) * 32 + hq - 1]; }
            else if (cx > 0) { m0 = halo[par + o];       m1 = halo[par + o + 1]; }
            else             { m0 = 0.f; m1 = 0.f; }
            s0 = make_float4(m0, g0.x, g0.y, g0.z);
            s1 = make_float4(m1, g1.x, g1.y, g1.z);
        } else {                 // shifted[h] = gated[h+1], 0 at global h=127
            float p0, p1;
            if (hq < 28)     { p0 = sg[o * 32 + hq + 4]; p1 = sg[(o + 1) * 32 + hq + 4]; }
            else if (cx < 3) { p0 = halo[par + o];       p1 = halo[par + o + 1]; }
            else             { p0 = 0.f; p1 = 0.f; }
            s0 = make_float4(g0.y, g0.z, g0.w, p0);
            s1 = make_float4(g1.y, g1.z, g1.w, p1);
        }

        const float ba0 = sba[o], ba1 = sba[o + 1];
        const float bb0 = sbb[o], bb1 = sbb[o + 1];
        float4 c0, c1;
        c0.x = fmaxf(aA0.x + ba0 + (aB0.x + bb0) * y0.x + gamma * s0.x, 0.f);
        c0.y = fmaxf(aA0.y + ba0 + (aB0.y + bb0) * y0.y + gamma * s0.y, 0.f);
        c0.z = fmaxf(aA0.z + ba0 + (aB0.z + bb0) * y0.z + gamma * s0.z, 0.f);
        c0.w = fmaxf(aA0.w + ba0 + (aB0.w + bb0) * y0.w + gamma * s0.w, 0.f);
        c1.x = fmaxf(aA1.x + ba1 + (aB1.x + bb1) * y1.x + gamma * s1.x, 0.f);
        c1.y = fmaxf(aA1.y + ba1 + (aB1.y + bb1) * y1.y + gamma * s1.y, 0.f);
        c1.z = fmaxf(aA1.z + ba1 + (aB1.z + bb1) * y1.z + gamma * s1.z, 0.f);
        c1.w = fmaxf(aA1.w + ba1 + (aB1.w + bb1) * y1.w + gamma * s1.w, 0.f);

        // state update (safe: all cp reads happened before the cluster barrier)
        *(float4*)(cp + o * 32 + hq) = c0;
        *(float4*)(cp + (o + 1) * 32 + hq) = c1;
        *(float4*)(outb + o * HWX + j * 128 + hq) = c0;
        *(float4*)(outb + (o + 1) * HWX + j * 128 + hq) = c1;
    }
}

// ===========================================================================
// Kernel 4: sum four direction buffers ([b][c][w][h]) and transpose to d_out.
// ===========================================================================
__global__ void __launch_bounds__(256, 1) sum_transpose_kernel(float* __restrict__ out)
{
    __shared__ float tile[32][33];
    const int n  = blockIdx.z;                 // b*64 + c
    const int w0 = blockIdx.y * 32, h0 = blockIdx.x * 32;
    const int tx = threadIdx.x & 31, ty = (threadIdx.x >> 5) * 4;
    const float* s0 = g_col[0] + n * HWX;
    const float* s1 = g_col[1] + n * HWX;
    const float* s2 = g_col[2] + n * HWX;
    const float* s3 = g_col[3] + n * HWX;
    #pragma unroll
    for (int k = 0; k < 4; ++k) {
        int idx = (w0 + ty + k) * 128 + h0 + tx;
        tile[ty + k][tx] = s0[idx] + s1[idx] + s2[idx] + s3[idx];
    }
    __syncthreads();
    float* d = out + n * HWX;
    #pragma unroll
    for (int k = 0; k < 4; ++k)
        d[(h0 + ty + k) * 128 + w0 + tx] = tile[tx][ty + k];
}

// ===========================================================================
extern "C" void kernel_launch(void* const* d_in, const int* in_sizes, int n_in,
                              void* d_out, int out_size)
{
    const float* x  = (const float*)d_in[0];
    const float* y  = (const float*)d_in[1];
    const float* Wc = (const float*)d_in[2];
    const float* bc = (const float*)d_in[3];
    const float* gm = (const float*)d_in[4];
    float* out = (float*)d_out;

    const int COLSMEM = 18752 * 4;  // 75008 B dynamic smem for col_scan_kernel
    cudaFuncSetAttribute(col_scan_kernel,
                         cudaFuncAttributeMaxDynamicSharedMemorySize, COLSMEM);

    row_scan_kernel<<<dim3(8, 8, 2), 256>>>(x, y, Wc, bc);
    transpose3_kernel<<<dim3(4, 4, 1536), 256>>>(y);
    col_scan_kernel<<<dim3(4, 8, 4), 256, COLSMEM>>>(Wc, bc, gm);
    sum_transpose_kernel<<<dim3(4, 4, 512), 256>>>(out);

    (void)in_sizes; (void)n_in; (void)out_size;
}

// round 7
// speedup vs baseline: 1.5730x; 1.5730x over previous
#include <cuda_runtime.h>
#include <cstdint>

// Problem dims
#define HWX  16384      // 128*128
#define CHWX 1048576    // 64*128*128
#define TOTX 8388608    // 8*64*128*128

typedef unsigned long long ull;

// ---------------- device scratch (allocation-free rule: device globals) ----
__device__ __align__(16) float g_hs [TOTX];   // south row-scan, natural [b][c][h][w]
__device__ __align__(16) float g_hn [TOTX];   // north row-scan, natural
__device__ __align__(16) float g_hsT[TOTX];   // [b][c][w][h]
__device__ __align__(16) float g_hnT[TOTX];
__device__ __align__(16) float g_yT [TOTX];   // y transposed [b][c][w][h]
__device__ __align__(16) float g_col[4][TOTX];// per-direction col-scan output, [b][c][w][h]

// ---------------- f32x2 helpers -------------------------------------------
__device__ __forceinline__ ull dup2(float w) {
    ull r; asm("mov.b64 %0, {%1, %1};" : "=l"(r) : "f"(w)); return r;
}
__device__ __forceinline__ void fma2(ull& acc, ull a, ull b) {
    asm("fma.rn.f32x2 %0, %1, %2, %0;" : "+l"(acc) : "l"(a), "l"(b));
}
__device__ __forceinline__ float2 unpk(ull v) {
    float2 f; asm("mov.b64 {%0, %1}, %2;" : "=f"(f.x), "=f"(f.y) : "l"(v)); return f;
}
__device__ __forceinline__ ull dal(double d) { return __double_as_longlong(d); }

// ---------------- cp.async helpers ----------------------------------------
__device__ __forceinline__ void cpasync16(void* s, const void* g) {
    uint32_t sa = (uint32_t)__cvta_generic_to_shared(s);
    asm volatile("cp.async.ca.shared.global [%0], [%1], 16;" :: "r"(sa), "l"(g) : "memory");
}
__device__ __forceinline__ void cpcommit() { asm volatile("cp.async.commit_group;" ::: "memory"); }
__device__ __forceinline__ void cpwait0()  { asm volatile("cp.async.wait_group 0;"  ::: "memory"); }

// DSMEM scalar store into peer CTA's shared memory (cluster rank `rank`)
__device__ __forceinline__ void dsmem_store(float* laddr, int rank, float v) {
    uint32_t la = (uint32_t)__cvta_generic_to_shared(laddr);
    uint32_t ra;
    asm volatile("mapa.shared::cluster.u32 %0, %1, %2;" : "=r"(ra) : "r"(la), "r"(rank));
    asm volatile("st.shared::cluster.f32 [%0], %1;" :: "r"(ra), "f"(v) : "memory");
}

__device__ __forceinline__ float4 relu4(float4 v) {
    v.x = fmaxf(v.x, 0.f); v.y = fmaxf(v.y, 0.f);
    v.z = fmaxf(v.z, 0.f); v.w = fmaxf(v.w, 0.f);
    return v;
}

extern __shared__ __align__(16) float smdyn[];

// ===========================================================================
// Kernel 1: row scans (south dir=0, north dir=1).
// grid (8 w-tiles, 8 batch, 2 dirs), 128 threads, dynamic smem.
// Thread tile: 4 out-channels x 2 w (one f32x2 pair). Weights [c][o] float4.
// x/y tiles double-buffered via cp.async.
// smem layout (floats): WaT 0, WbT 4096, sx 8192(2x1024), sy 10240(2x1024),
//                       sh 12288, ba 13312, bb 13376  -> 13440 fl = 53760 B
// ===========================================================================
__global__ void __launch_bounds__(128, 1) row_scan_kernel(
    const float* __restrict__ x, const float* __restrict__ y,
    const float* __restrict__ Wc, const float* __restrict__ bc)
{
    float* sWaT = smdyn;
    float* sWbT = smdyn + 4096;
    float* sx   = smdyn + 8192;
    float* sy   = smdyn + 10240;
    float* sh   = smdyn + 12288;
    float* sba  = smdyn + 13312;
    float* sbb  = smdyn + 13376;

    const int dir = blockIdx.z;          // 0 = south, 1 = north
    const int b   = blockIdx.y;
    const int w0  = blockIdx.x * 16;
    const int t   = threadIdx.x;

    const int ka = dir ? 8 : 0;
    const float* Wa = Wc + ka * 4096;
    const float* Wb = Wc + (ka + 1) * 4096;
    for (int idx = t; idx < 4096; idx += 128) {
        int o = idx >> 6, c = idx & 63;
        sWaT[c * 64 + o] = Wa[idx];
        sWbT[c * 64 + o] = Wb[idx];
    }
    if (t < 64) { sba[t] = bc[ka * 64 + t]; sbb[t] = bc[(ka + 1) * 64 + t]; }

    const float* xb = x + b * CHWX + w0;
    const float* yb = y + b * CHWX + w0;
    float* hb = (dir ? g_hn : g_hs) + b * CHWX + w0;

    // boundary row init: 8 floats per thread
    {
        const int r0 = dir ? 127 : 0;
        const int c  = t >> 1;
        const int wv = (t & 1) * 8;
        #pragma unroll
        for (int kk = 0; kk < 2; ++kk) {
            float4 v = *(const float4*)(xb + c * HWX + r0 * 128 + wv + kk * 4);
            if (dir) v = relu4(v);
            *(float4*)(sh + c * 16 + wv + kk * 4) = v;
            *(float4*)(hb + c * HWX + r0 * 128 + wv + kk * 4) = v;
        }
    }
    // prefetch step 1 tiles into parity-1 buffers
    {
        const int r2  = dir ? 126 : 1;
        const int yr2 = dir ? 127 : 0;
        #pragma unroll
        for (int k = 0; k < 2; ++k) {
            int q = t + 128 * k;
            int c = q >> 2, w = (q & 3) * 4;
            cpasync16(sx + 1024 + c * 16 + w, xb + c * HWX + r2  * 128 + w);
            cpasync16(sy + 1024 + c * 16 + w, yb + c * HWX + yr2 * 128 + w);
        }
        cpcommit();
    }

    const int o4 = (t >> 3) * 4;         // 4 out-channels
    const int wq = (t & 7) * 2;          // one w pair

    for (int i = 1; i < 128; ++i) {
        const int p = i & 1;
        const float* sxP = sx + p * 1024;
        const float* syP = sy + p * 1024;
        const int r = dir ? 127 - i : i;

        cpwait0();
        __syncthreads();

        if (i < 127) {
            const int r2  = dir ? 127 - (i + 1) : (i + 1);
            const int yr2 = dir ? r2 + 1 : r2 - 1;
            float* sxN = sx + (1 - p) * 1024;
            float* syN = sy + (1 - p) * 1024;
            #pragma unroll
            for (int k = 0; k < 2; ++k) {
                int q = t + 128 * k;
                int c = q >> 2, w = (q & 3) * 4;
                cpasync16(sxN + c * 16 + w, xb + c * HWX + r2  * 128 + w);
                cpasync16(syN + c * 16 + w, yb + c * HWX + yr2 * 128 + w);
            }
            cpcommit();
        }

        ull aa[4], ab[4];
        #pragma unroll
        for (int k = 0; k < 4; ++k) { aa[k] = 0ULL; ab[k] = 0ULL; }

        #pragma unroll 4
        for (int c = 0; c < 64; ++c) {
            ull xv = dal(*(const double*)(sxP + c * 16 + wq));
            ull hv = dal(*(const double*)(sh  + c * 16 + wq));
            float4 wa = *(const float4*)(sWaT + c * 64 + o4);
            float4 wb = *(const float4*)(sWbT + c * 64 + o4);
            float wa4[4] = {wa.x, wa.y, wa.z, wa.w};
            float wb4[4] = {wb.x, wb.y, wb.z, wb.w};
            #pragma unroll
            for (int k = 0; k < 4; ++k) {
                fma2(aa[k], xv, dup2(wa4[k]));
                fma2(ab[k], hv, dup2(wb4[k]));
            }
        }

        float2 res[4];
        #pragma unroll
        for (int k = 0; k < 4; ++k) {
            const int o = o4 + k;
            float2 A  = unpk(aa[k]);
            float2 Bv = unpk(ab[k]);
            float2 yv = *(const float2*)(syP + o * 16 + wq);
            const float ba_ = sba[o], bb_ = sbb[o];
            res[k].x = fmaxf(A.x + ba_ + (Bv.x + bb_) * yv.x, 0.f);
            res[k].y = fmaxf(A.y + ba_ + (Bv.y + bb_) * yv.y, 0.f);
        }
        __syncthreads();
        #pragma unroll
        for (int k = 0; k < 4; ++k) {
            const int o = o4 + k;
            *(float2*)(sh + o * 16 + wq) = res[k];
            *(float2*)(hb + o * HWX + r * 128 + wq) = res[k];
        }
    }
}

// ===========================================================================
// Kernel 2: batched 128x128 transpose of last two dims.
// blockIdx.z: [0,512)=y->yT, [512,1024)=hs->hsT, [1024,1536)=hn->hnT
// ===========================================================================
__global__ void __launch_bounds__(256, 1) transpose3_kernel(const float* __restrict__ ysrc)
{
    __shared__ float tile[32][33];
    const int mode = blockIdx.z >> 9;
    const int n    = blockIdx.z & 511;
    const float* src = (mode == 0 ? ysrc : (mode == 1 ? g_hs : g_hn)) + n * HWX;
    float*       dst = (mode == 0 ? g_yT : (mode == 1 ? g_hsT : g_hnT)) + n * HWX;
    const int r0 = blockIdx.y * 32, c0 = blockIdx.x * 32;
    const int tx = threadIdx.x & 31, ty = (threadIdx.x >> 5) * 4;
    #pragma unroll
    for (int k = 0; k < 4; ++k) tile[ty + k][tx] = src[(r0 + ty + k) * 128 + c0 + tx];
    __syncthreads();
    #pragma unroll
    for (int k = 0; k < 4; ++k) dst[(c0 + ty + k) * 128 + r0 + tx] = tile[tx][ty + k];
}

// ===========================================================================
// Kernel 3: column scans, all 4 directions in one launch.
// grid (4 H-chunks [cluster 4], 8 batch, 4 dirs), 128 threads, dynamic smem.
// Thread tile: 4 out-channels x 4 h (two f32x2 pairs). f32x2 mainloop,
// scalar epilogue. Base column double-buffered via cp.async; y prefetched
// to registers. One gated boundary row exchanged per step via DSMEM.
// smem (floats): WtT 0, WaT 4096, WbT 8192, bs 12288(2x2048), cp 16384,
//                sg 18432, halo 20480(2x64), bt 20608, ba 20672, bb 20736
//                -> 20800 fl = 83200 B
// ===========================================================================
__global__ void __launch_bounds__(128, 1) __cluster_dims__(4, 1, 1)
col_scan_kernel(const float* __restrict__ Wc, const float* __restrict__ bc,
                const float* __restrict__ gms)
{
    float* sWtT = smdyn;
    float* sWaT = smdyn + 4096;
    float* sWbT = smdyn + 8192;
    float* bsB  = smdyn + 12288;
    float* cp   = smdyn + 16384;
    float* sg   = smdyn + 18432;
    float* halo = smdyn + 20480;
    float* sbt  = smdyn + 20608;
    float* sba  = smdyn + 20672;
    float* sbb  = smdyn + 20736;

    const int dir = blockIdx.z;     // 0 hse, 1 hsw, 2 hne, 3 hnw
    const int b   = blockIdx.y;
    const int cx  = blockIdx.x;     // cluster rank
    const int r0  = cx * 32;
    const int t   = threadIdx.x;

    int kt;
    if (dir == 0) kt = 2; else if (dir == 1) kt = 5; else if (dir == 2) kt = 10; else kt = 13;
    const int  wdir = (dir & 1) ? -1 : 1;
    const bool shup = (dir >= 2);
    const float gamma = gms[dir];

    for (int idx = t; idx < 4096; idx += 128) {
        int o = idx >> 6, c = idx & 63;
        sWtT[c * 64 + o] = Wc[kt * 4096 + idx];
        sWaT[c * 64 + o] = Wc[(kt + 1) * 4096 + idx];
        sWbT[c * 64 + o] = Wc[(kt + 2) * 4096 + idx];
    }
    if (t < 64) {
        sbt[t] = bc[kt * 64 + t];
        sba[t] = bc[(kt + 1) * 64 + t];
        sbb[t] = bc[(kt + 2) * 64 + t];
    }

    const float* baseb = ((dir < 2) ? g_hsT : g_hnT) + b * CHWX + r0;  // [c][w][h]
    const float* yTb   = g_yT + b * CHWX + r0;
    float*       outb  = g_col[dir] + b * CHWX + r0;

    // init column j0: 16 floats per thread
    {
        const int j0 = (wdir > 0) ? 0 : 127;
        const int c  = t >> 1;
        const int h0 = (t & 1) * 16;
        #pragma unroll
        for (int kk = 0; kk < 4; ++kk) {
            float4 v = relu4(*(const float4*)(baseb + c * HWX + j0 * 128 + h0 + kk * 4));
            *(float4*)(cp + c * 32 + h0 + kk * 4) = v;
            *(float4*)(outb + c * HWX + j0 * 128 + h0 + kk * 4) = v;
        }
    }
    // prefetch base column for step 1 into parity-1 buffer
    {
        const int j1 = (wdir > 0) ? 1 : 126;
        float* nb = bsB + 2048;
        #pragma unroll
        for (int k = 0; k < 4; ++k) {
            int q = t + 128 * k;
            int c = q >> 3, h = (q & 7) * 4;
            cpasync16(nb + c * 32 + h, baseb + c * HWX + j1 * 128 + h);
        }
        cpcommit();
    }

    const int o4 = (t >> 3) * 4;       // 4 out-channels
    const int hq = (t & 7) * 4;        // 4 local h rows

    for (int jj = 1; jj < 128; ++jj) {
        const int p = jj & 1;
        const float* bsP = bsB + p * 2048;
        const int j  = (wdir > 0) ? jj : 127 - jj;
        const int yj = j - wdir;

        cpwait0();
        __syncthreads();

        if (jj < 127) {
            const int j2 = (wdir > 0) ? jj + 1 : 126 - jj;
            float* nb = bsB + (1 - p) * 2048;
            #pragma unroll
            for (int k = 0; k < 4; ++k) {
                int q = t + 128 * k;
                int c = q >> 3, h = (q & 7) * 4;
                cpasync16(nb + c * 32 + h, baseb + c * HWX + j2 * 128 + h);
            }
            cpcommit();
        }

        float4 yv[4];
        #pragma unroll
        for (int k = 0; k < 4; ++k)
            yv[k] = *(const float4*)(yTb + (o4 + k) * HWX + yj * 128 + hq);

        ull aT[4][2], aA[4][2], aB[4][2];
        #pragma unroll
        for (int k = 0; k < 4; ++k) {
            aT[k][0] = aT[k][1] = 0ULL;
            aA[k][0] = aA[k][1] = 0ULL;
            aB[k][0] = aB[k][1] = 0ULL;
        }

        #pragma unroll 4
        for (int c = 0; c < 64; ++c) {
            double2 bv = *(const double2*)(bsP + c * 32 + hq);
            double2 pv = *(const double2*)(cp  + c * 32 + hq);
            ull b0 = dal(bv.x), b1 = dal(bv.y);
            ull p0 = dal(pv.x), p1 = dal(pv.y);
            float4 wt = *(const float4*)(sWtT + c * 64 + o4);
            float4 wa = *(const float4*)(sWaT + c * 64 + o4);
            float4 wb = *(const float4*)(sWbT + c * 64 + o4);
            float wt4[4] = {wt.x, wt.y, wt.z, wt.w};
            float wa4[4] = {wa.x, wa.y, wa.z, wa.w};
            float wb4[4] = {wb.x, wb.y, wb.z, wb.w};
            #pragma unroll
            for (int k = 0; k < 4; ++k) {
                ull w;
                w = dup2(wt4[k]); fma2(aT[k][0], p0, w); fma2(aT[k][1], p1, w);
                w = dup2(wa4[k]); fma2(aA[k][0], b0, w); fma2(aA[k][1], b1, w);
                w = dup2(wb4[k]); fma2(aB[k][0], p0, w); fma2(aB[k][1], p1, w);
            }
        }

        // gating (scalar epilogue)
        float g[4][4];
        #pragma unroll
        for (int k = 0; k < 4; ++k) {
            float2 t0 = unpk(aT[k][0]), t1 = unpk(aT[k][1]);
            const float bt_ = sbt[o4 + k];
            g[k][0] = (t0.x + bt_) * yv[k].x;
            g[k][1] = (t0.y + bt_) * yv[k].y;
            g[k][2] = (t1.x + bt_) * yv[k].z;
            g[k][3] = (t1.y + bt_) * yv[k].w;
            *(float4*)(sg + (o4 + k) * 32 + hq) =
                make_float4(g[k][0], g[k][1], g[k][2], g[k][3]);
        }

        // export boundary gated row to H-neighbor's halo (parity double-buffer)
        const int par = (jj & 1) * 64;
        if (!shup) {             // shift_down: my last local row -> cx+1
            if (hq == 28 && cx < 3) {
                #pragma unroll
                for (int k = 0; k < 4; ++k)
                    dsmem_store(halo + par + o4 + k, cx + 1, g[k][3]);
            }
        } else {                 // shift_up: my first local row -> cx-1
            if (hq == 0 && cx > 0) {
                #pragma unroll
                for (int k = 0; k < 4; ++k)
                    dsmem_store(halo + par + o4 + k, cx - 1, g[k][0]);
            }
        }
        asm volatile("barrier.cluster.arrive.aligned;" ::: "memory");
        asm volatile("barrier.cluster.wait.aligned;"   ::: "memory");

        #pragma unroll
        for (int k = 0; k < 4; ++k) {
            const int o = o4 + k;
            float s0, s1, s2, s3;
            if (!shup) {         // shifted[h] = gated[h-1], 0 at global h=0
                float m;
                if (hq > 0)      m = sg[o * 32 + hq - 1];
                else if (cx > 0) m = halo[par + o];
                else             m = 0.f;
                s0 = m; s1 = g[k][0]; s2 = g[k][1]; s3 = g[k][2];
            } else {             // shifted[h] = gated[h+1], 0 at global h=127
                float q_;
                if (hq < 28)     q_ = sg[o * 32 + hq + 4];
                else if (cx < 3) q_ = halo[par + o];
                else             q_ = 0.f;
                s0 = g[k][1]; s1 = g[k][2]; s2 = g[k][3]; s3 = q_;
            }
            float2 A0 = unpk(aA[k][0]), A1 = unpk(aA[k][1]);
            float2 B0 = unpk(aB[k][0]), B1 = unpk(aB[k][1]);
            const float ba_ = sba[o], bb_ = sbb[o];
            float4 cres;
            cres.x = fmaxf(A0.x + ba_ + (B0.x + bb_) * yv[k].x + gamma * s0, 0.f);
            cres.y = fmaxf(A0.y + ba_ + (B0.y + bb_) * yv[k].y + gamma * s1, 0.f);
            cres.z = fmaxf(A1.x + ba_ + (B1.x + bb_) * yv[k].z + gamma * s2, 0.f);
            cres.w = fmaxf(A1.y + ba_ + (B1.y + bb_) * yv[k].w + gamma * s3, 0.f);
            *(float4*)(cp + o * 32 + hq) = cres;
            *(float4*)(outb + o * HWX + j * 128 + hq) = cres;
        }
    }
}

// ===========================================================================
// Kernel 4: sum four direction buffers ([b][c][w][h]) and transpose to d_out.
// ===========================================================================
__global__ void __launch_bounds__(256, 1) sum_transpose_kernel(float* __restrict__ out)
{
    __shared__ float tile[32][33];
    const int n  = blockIdx.z;                 // b*64 + c
    const int w0 = blockIdx.y * 32, h0 = blockIdx.x * 32;
    const int tx = threadIdx.x & 31, ty = (threadIdx.x >> 5) * 4;
    const float* s0 = g_col[0] + n * HWX;
    const float* s1 = g_col[1] + n * HWX;
    const float* s2 = g_col[2] + n * HWX;
    const float* s3 = g_col[3] + n * HWX;
    #pragma unroll
    for (int k = 0; k < 4; ++k) {
        int idx = (w0 + ty + k) * 128 + h0 + tx;
        tile[ty + k][tx] = s0[idx] + s1[idx] + s2[idx] + s3[idx];
    }
    __syncthreads();
    float* d = out + n * HWX;
    #pragma unroll
    for (int k = 0; k < 4; ++k)
        d[(h0 + ty + k) * 128 + w0 + tx] = tile[tx][ty + k];
}

// ===========================================================================
extern "C" void kernel_launch(void* const* d_in, const int* in_sizes, int n_in,
                              void* d_out, int out_size)
{
    const float* x  = (const float*)d_in[0];
    const float* y  = (const float*)d_in[1];
    const float* Wc = (const float*)d_in[2];
    const float* bc = (const float*)d_in[3];
    const float* gm = (const float*)d_in[4];
    float* out = (float*)d_out;

    const int ROWSMEM = 13440 * 4;  // 53760 B
    const int COLSMEM = 20800 * 4;  // 83200 B
    cudaFuncSetAttribute(row_scan_kernel,
                         cudaFuncAttributeMaxDynamicSharedMemorySize, ROWSMEM);
    cudaFuncSetAttribute(col_scan_kernel,
                         cudaFuncAttributeMaxDynamicSharedMemorySize, COLSMEM);

    row_scan_kernel<<<dim3(8, 8, 2), 128, ROWSMEM>>>(x, y, Wc, bc);
    transpose3_kernel<<<dim3(4, 4, 1536), 256>>>(y);
    col_scan_kernel<<<dim3(4, 8, 4), 128, COLSMEM>>>(Wc, bc, gm);
    sum_transpose_kernel<<<dim3(4, 4, 512), 256>>>(out);

    (void)in_sizes; (void)n_in; (void)out_size;
}